// round 2
// baseline (speedup 1.0000x reference)
#include <cuda_runtime.h>
#include <cuda_bf16.h>

// Problem constants: x = (8, 3, 1024, 1024) float32
#define BATCH 8
#define HDIM  1024
#define WDIM  1024
#define HW    (HDIM * WDIM)          // 1<<20
#define HW4   (HW / 4)               // 1<<18

#define TILE_W 32
#define TILE_H 32
#define BLK_X  32
#define BLK_Y  8
#define ROWS_PER_THREAD (TILE_H / BLK_Y)   // 4
#define BLOCKS_PER_BATCH ((HDIM / TILE_H) * (WDIM / TILE_W))  // 1024

// Scratch: t = g - S (32 MB), per-block partial sums, per-batch stats.
__device__ float g_t[BATCH * HW];
__device__ float g_psum[BATCH][BLOCKS_PER_BATCH];
__device__ float g_psum2[BATCH][BLOCKS_PER_BATCH];
__device__ float2 g_stats[BATCH];   // (mean, rstd)

// Neighbor weights, indexed by (di+1, dj+1) relative position.
// OFFSETS j: (0,-1)=1, (1,-1)=2, (1,0)=4, (1,1)=8, (0,1)=16, (-1,1)=32, (-1,0)=64, (-1,-1)=128 (all /255)
__device__ __forceinline__ float stencil(const float gs[TILE_H + 2][TILE_W + 4], int ly, int lx) {
    const float c = gs[ly + 1][lx + 1];
    float S;
    S  = (128.0f / 255.0f) * gs[ly + 0][lx + 0];  // (-1,-1)
    S += ( 64.0f / 255.0f) * gs[ly + 0][lx + 1];  // (-1, 0)
    S += ( 32.0f / 255.0f) * gs[ly + 0][lx + 2];  // (-1, 1)
    S += (  1.0f / 255.0f) * gs[ly + 1][lx + 0];  // ( 0,-1)
    S += ( 16.0f / 255.0f) * gs[ly + 1][lx + 2];  // ( 0, 1)
    S += (  2.0f / 255.0f) * gs[ly + 2][lx + 0];  // ( 1,-1)
    S += (  4.0f / 255.0f) * gs[ly + 2][lx + 1];  // ( 1, 0)
    S += (  8.0f / 255.0f) * gs[ly + 2][lx + 2];  // ( 1, 1)
    return c - S;
}

__global__ __launch_bounds__(256) void ltpe_stencil_kernel(const float* __restrict__ x) {
    __shared__ float gs[TILE_H + 2][TILE_W + 4];  // +4 col pad (bank-shift)

    const int bx = blockIdx.x;          // tile col
    const int by = blockIdx.y;          // tile row
    const int b  = blockIdx.z;          // batch
    const int tx = threadIdx.x;         // 0..31
    const int ty = threadIdx.y;         // 0..7
    const int tid = ty * BLK_X + tx;

    const float* xb0 = x + (size_t)b * 3 * HW;            // channel 0
    const float* xb1 = xb0 + HW;
    const float* xb2 = xb0 + 2 * HW;

    const int y0 = by * TILE_H;
    const int x0 = bx * TILE_W;

    // Load (TILE_H+2) x (TILE_W+2) grayscale halo (zero pad outside image).
    const int HALO_W = TILE_W + 2;
    const int HALO = (TILE_H + 2) * HALO_W;
    for (int i = tid; i < HALO; i += BLK_X * BLK_Y) {
        int r = i / HALO_W;
        int c = i - r * HALO_W;
        int gy = y0 + r - 1;
        int gx = x0 + c - 1;
        float val = 0.0f;
        if (gy >= 0 && gy < HDIM && gx >= 0 && gx < WDIM) {
            int idx = gy * WDIM + gx;
            val = 0.30f * xb0[idx] + 0.59f * xb1[idx] + 0.11f * xb2[idx];
        }
        gs[r][c] = val;
    }
    __syncthreads();

    float s = 0.0f, s2 = 0.0f;
    float* tb = g_t + (size_t)b * HW;
#pragma unroll
    for (int k = 0; k < ROWS_PER_THREAD; k++) {
        int ly = ty * ROWS_PER_THREAD + k;
        float t = stencil(gs, ly, tx);
        tb[(size_t)(y0 + ly) * WDIM + (x0 + tx)] = t;
        s  += t;
        s2 += t * t;
    }

    // Block reduction (warp shuffle + smem across 8 warps). Deterministic.
#pragma unroll
    for (int off = 16; off > 0; off >>= 1) {
        s  += __shfl_down_sync(0xffffffffu, s,  off);
        s2 += __shfl_down_sync(0xffffffffu, s2, off);
    }
    __shared__ float ws[BLK_Y], ws2[BLK_Y];
    if (tx == 0) { ws[ty] = s; ws2[ty] = s2; }
    __syncthreads();
    if (tid == 0) {
        float bs = 0.0f, bs2 = 0.0f;
#pragma unroll
        for (int w = 0; w < BLK_Y; w++) { bs += ws[w]; bs2 += ws2[w]; }
        int pidx = by * (WDIM / TILE_W) + bx;
        g_psum[b][pidx]  = bs;
        g_psum2[b][pidx] = bs2;
    }
}

__global__ __launch_bounds__(256) void ltpe_reduce_kernel() {
    const int b = blockIdx.x;
    const int tid = threadIdx.x;
    float s = 0.0f, s2 = 0.0f;
#pragma unroll
    for (int i = 0; i < BLOCKS_PER_BATCH / 256; i++) {
        int idx = i * 256 + tid;
        s  += g_psum[b][idx];
        s2 += g_psum2[b][idx];
    }
#pragma unroll
    for (int off = 16; off > 0; off >>= 1) {
        s  += __shfl_down_sync(0xffffffffu, s,  off);
        s2 += __shfl_down_sync(0xffffffffu, s2, off);
    }
    __shared__ float ws[8], ws2[8];
    int wid = tid / 32;
    if ((tid & 31) == 0) { ws[wid] = s; ws2[wid] = s2; }
    __syncthreads();
    if (tid == 0) {
        float bs = 0.0f, bs2 = 0.0f;
#pragma unroll
        for (int w = 0; w < 8; w++) { bs += ws[w]; bs2 += ws2[w]; }
        float mean = bs * (1.0f / (float)HW);
        float var  = bs2 * (1.0f / (float)HW) - mean * mean;
        // out = 0.5*t + 0.5; normalize(out) == (t - mean_t) * rsqrt(var_t + 4*EPS)
        float rstd = rsqrtf(var + 4.0f * 1e-5f);
        g_stats[b] = make_float2(mean, rstd);
    }
}

__global__ __launch_bounds__(256) void ltpe_normalize_kernel(float* __restrict__ out) {
    // float4-vectorized, grid-stride: BATCH*HW/4 = 2M float4s total
    const int total = BATCH * HW4;
    const float4* tv = reinterpret_cast<const float4*>(g_t);
    float4* ov = reinterpret_cast<float4*>(out);

    for (int i = blockIdx.x * blockDim.x + threadIdx.x; i < total;
         i += gridDim.x * blockDim.x) {
        const int b = i >> 18;                // i / HW4
        const int p = i & (HW4 - 1);          // float4 index within plane

        float2 st = g_stats[b];
        float4 t = tv[i];
        float4 r;
        r.x = (t.x - st.x) * st.y;
        r.y = (t.y - st.x) * st.y;
        r.z = (t.z - st.x) * st.y;
        r.w = (t.w - st.x) * st.y;

        size_t base = (size_t)b * 3 * HW4;
        ov[base + 0 * HW4 + p] = r;
        ov[base + 1 * HW4 + p] = r;
        ov[base + 2 * HW4 + p] = r;
    }
}

extern "C" void kernel_launch(void* const* d_in, const int* in_sizes, int n_in,
                              void* d_out, int out_size) {
    const float* x = (const float*)d_in[0];
    float* out = (float*)d_out;

    dim3 grid1(WDIM / TILE_W, HDIM / TILE_H, BATCH);
    dim3 blk1(BLK_X, BLK_Y);
    ltpe_stencil_kernel<<<grid1, blk1>>>(x);

    ltpe_reduce_kernel<<<BATCH, 256>>>();

    int n4 = BATCH * HW4;
    ltpe_normalize_kernel<<<n4 / 256, 256>>>(out);
}

// round 5
// speedup vs baseline: 1.1489x; 1.1489x over previous
#include <cuda_runtime.h>
#include <cuda_bf16.h>

// Problem constants: x = (8, 3, 1024, 1024) float32
#define BATCH 8
#define HDIM  1024
#define WDIM  1024
#define HW    (HDIM * WDIM)          // 1<<20
#define HW4   (HW / 4)               // 1<<18

#define BAND  16                     // rows per block
#define NBANDS (HDIM / BAND)         // 64

// Scratch: t = g - S (32 MB), per-band partial sums, per-batch stats.
__device__ float g_t[BATCH * HW];
__device__ float g_psum[BATCH][NBANDS];
__device__ float g_psum2[BATCH][NBANDS];
__device__ float2 g_stats[BATCH];    // (mean, rstd)

// Stencil weights /255, by (di,dj):
// (-1,-1)=128 (-1,0)=64 (-1,1)=32 (0,-1)=1 (0,1)=16 (1,-1)=2 (1,0)=4 (1,1)=8
#define C128 (128.0f/255.0f)
#define C64  ( 64.0f/255.0f)
#define C32  ( 32.0f/255.0f)
#define C16  ( 16.0f/255.0f)
#define C8   (  8.0f/255.0f)
#define C4   (  4.0f/255.0f)
#define C2   (  2.0f/255.0f)
#define C1   (  1.0f/255.0f)

__device__ __forceinline__ float4 gray4(float4 a, float4 b, float4 c) {
    float4 g;
    g.x = 0.30f*a.x + 0.59f*b.x + 0.11f*c.x;
    g.y = 0.30f*a.y + 0.59f*b.y + 0.11f*c.y;
    g.z = 0.30f*a.z + 0.59f*b.z + 0.11f*c.z;
    g.w = 0.30f*a.w + 0.59f*b.w + 0.11f*c.w;
    return g;
}

__device__ __forceinline__ void load_row(const float* __restrict__ p0,
                                         const float* __restrict__ p1,
                                         const float* __restrict__ p2,
                                         int y, float4& r0, float4& r1, float4& r2) {
    if (y >= 0 && y < HDIM) {
        size_t off = (size_t)y * WDIM;
        r0 = __ldg((const float4*)(p0 + off));
        r1 = __ldg((const float4*)(p1 + off));
        r2 = __ldg((const float4*)(p2 + off));
    } else {
        r0 = r1 = r2 = make_float4(0.f, 0.f, 0.f, 0.f);
    }
}

// block = 256 threads = 8 warps; warp w owns column strip [128w, 128w+128)
// Each thread: one float4 per row per channel at col = 128w + 4*lane.
__global__ __launch_bounds__(256) void ltpe_stencil_kernel(const float* __restrict__ x) {
    __shared__ float eL[2][8], eR[2][8];   // per-row strip-edge exchange (2 rotating slots)
    __shared__ float ws[8], ws2[8];

    const int band = blockIdx.x;
    const int b    = blockIdx.y;
    const int w    = threadIdx.x >> 5;
    const int lane = threadIdx.x & 31;
    const int col  = (w << 7) + (lane << 2);
    const int y0   = band * BAND;

    const float* p0 = x + (size_t)b * 3 * HW + col;   // ch0 at this column
    const float* p1 = p0 + HW;
    const float* p2 = p0 + 2 * HW;

    float4 t0, t1, t2;
    float4 A, B, C;                 // gray rows y-1, y, y+1
    float lA, rA, lB, rB;           // carried edge scalars

    // ---- preload row y0-1 -> A (slot 0) ----
    load_row(p0, p1, p2, y0 - 1, t0, t1, t2);
    A = gray4(t0, t1, t2);
    if (lane == 0)  eL[0][w] = A.x;
    if (lane == 31) eR[0][w] = A.w;
    __syncthreads();
    {
        float up = __shfl_up_sync(0xffffffffu, A.w, 1);
        float dn = __shfl_down_sync(0xffffffffu, A.x, 1);
        lA = (lane == 0)  ? (w > 0 ? eR[0][w - 1] : 0.f) : up;
        rA = (lane == 31) ? (w < 7 ? eL[0][w + 1] : 0.f) : dn;
    }

    // ---- preload row y0 -> B (slot 1) ----
    load_row(p0, p1, p2, y0, t0, t1, t2);
    B = gray4(t0, t1, t2);
    if (lane == 0)  eL[1][w] = B.x;
    if (lane == 31) eR[1][w] = B.w;
    __syncthreads();
    {
        float up = __shfl_up_sync(0xffffffffu, B.w, 1);
        float dn = __shfl_down_sync(0xffffffffu, B.x, 1);
        lB = (lane == 0)  ? (w > 0 ? eR[1][w - 1] : 0.f) : up;
        rB = (lane == 31) ? (w < 7 ? eL[1][w + 1] : 0.f) : dn;
    }

    // ---- prefetch raw channels of row y0+1 ----
    float4 P0, P1, P2;
    load_row(p0, p1, p2, y0 + 1, P0, P1, P2);

    float s = 0.f, s2 = 0.f;
    float4* tb = (float4*)(g_t + (size_t)b * HW + col);

#pragma unroll 4
    for (int r = 0; r < BAND; r++) {
        const int y = y0 + r;
        // consume prefetched row y+1, prefetch row y+2
        float4 q0 = P0, q1 = P1, q2 = P2;
        load_row(p0, p1, p2, y + 2, P0, P1, P2);
        C = gray4(q0, q1, q2);

        const int slot = r & 1;
        if (lane == 0)  eL[slot][w] = C.x;
        if (lane == 31) eR[slot][w] = C.w;
        __syncthreads();
        float up = __shfl_up_sync(0xffffffffu, C.w, 1);
        float dn = __shfl_down_sync(0xffffffffu, C.x, 1);
        float lC = (lane == 0)  ? (w > 0 ? eR[slot][w - 1] : 0.f) : up;
        float rC = (lane == 31) ? (w < 7 ? eL[slot][w + 1] : 0.f) : dn;

        float4 t;
        t.x = B.x - (C128*lA  + C64*A.x + C32*A.y + C1*lB  + C16*B.y + C2*lC  + C4*C.x + C8*C.y);
        t.y = B.y - (C128*A.x + C64*A.y + C32*A.z + C1*B.x + C16*B.z + C2*C.x + C4*C.y + C8*C.z);
        t.z = B.z - (C128*A.y + C64*A.z + C32*A.w + C1*B.y + C16*B.w + C2*C.y + C4*C.z + C8*C.w);
        t.w = B.w - (C128*A.z + C64*A.w + C32*rA  + C1*B.z + C16*rB  + C2*C.z + C4*C.w + C8*rC);

        tb[(size_t)y * (WDIM / 4)] = t;
        s  += (t.x + t.y) + (t.z + t.w);
        s2 += (t.x*t.x + t.y*t.y) + (t.z*t.z + t.w*t.w);

        A = B; B = C;
        lA = lB; lB = lC;
        rA = rB; rB = rC;
    }

    // block reduction (deterministic)
#pragma unroll
    for (int off = 16; off > 0; off >>= 1) {
        s  += __shfl_down_sync(0xffffffffu, s,  off);
        s2 += __shfl_down_sync(0xffffffffu, s2, off);
    }
    if (lane == 0) { ws[w] = s; ws2[w] = s2; }
    __syncthreads();
    if (threadIdx.x == 0) {
        float bs = 0.f, bs2 = 0.f;
#pragma unroll
        for (int i = 0; i < 8; i++) { bs += ws[i]; bs2 += ws2[i]; }
        g_psum[b][band]  = bs;
        g_psum2[b][band] = bs2;
    }
}

// One block, 8 warps: warp b reduces batch b's 64 partials.
__global__ __launch_bounds__(256) void ltpe_reduce_kernel() {
    const int w    = threadIdx.x >> 5;   // batch
    const int lane = threadIdx.x & 31;
    float s  = g_psum[w][lane]  + g_psum[w][lane + 32];
    float s2 = g_psum2[w][lane] + g_psum2[w][lane + 32];
#pragma unroll
    for (int off = 16; off > 0; off >>= 1) {
        s  += __shfl_down_sync(0xffffffffu, s,  off);
        s2 += __shfl_down_sync(0xffffffffu, s2, off);
    }
    if (lane == 0) {
        float mean = s * (1.0f / (float)HW);
        float var  = s2 * (1.0f / (float)HW) - mean * mean;
        // out = 0.5*t + 0.5; normalize(out) == (t - mean_t) * rsqrt(var_t + 4*EPS)
        float rstd = rsqrtf(var + 4.0f * 1e-5f);
        g_stats[w] = make_float2(mean, rstd);
    }
}

__global__ __launch_bounds__(256) void ltpe_normalize_kernel(float* __restrict__ out) {
    const int total = BATCH * HW4;
    const float4* tv = reinterpret_cast<const float4*>(g_t);
    float4* ov = reinterpret_cast<float4*>(out);

    for (int i = blockIdx.x * blockDim.x + threadIdx.x; i < total;
         i += gridDim.x * blockDim.x) {
        const int b = i >> 18;               // i / HW4
        const int p = i & (HW4 - 1);
        float2 st = g_stats[b];
        float4 t = tv[i];
        float4 r;
        r.x = (t.x - st.x) * st.y;
        r.y = (t.y - st.x) * st.y;
        r.z = (t.z - st.x) * st.y;
        r.w = (t.w - st.x) * st.y;
        size_t base = (size_t)b * 3 * HW4;
        ov[base + 0 * HW4 + p] = r;
        ov[base + 1 * HW4 + p] = r;
        ov[base + 2 * HW4 + p] = r;
    }
}

extern "C" void kernel_launch(void* const* d_in, const int* in_sizes, int n_in,
                              void* d_out, int out_size) {
    const float* x = (const float*)d_in[0];
    float* out = (float*)d_out;

    dim3 grid1(NBANDS, BATCH);
    ltpe_stencil_kernel<<<grid1, 256>>>(x);

    ltpe_reduce_kernel<<<1, 256>>>();

    int n4 = BATCH * HW4;
    ltpe_normalize_kernel<<<n4 / 256, 256>>>(out);
}